// round 3
// baseline (speedup 1.0000x reference)
#include <cuda_runtime.h>

// depthconv1d: B=8, L=16384, C=512, K=31, SAME padding, fp32 NWC.
// out[b,w,c] = sum_k x[b, w+k-15, c] * ker[k*C + c] + bias[c]
//
// R3 (= R2 resubmitted after infra failure): k-outer loop, rolling x-ring in
// registers (XW=18 slots), weights streamed (double-buffered, L1-resident).
// Register footprint <=85 so 3 CTAs of 256 threads co-reside -> 24 warps/SM,
// hiding the DRAM latency that limited R1 (occ 22.5%, issue 38.6%).

#define B_ 8
#define L_ 16384
#define C_ 512
#define K_ 31
#define HALF_ 15
#define T_ 16      // output rows per thread
#define XW_ 18     // x ring slots (16 live + 2 prefetch slack)
#define NP_ (T_ + K_ - 1)   // 46 input rows per tile

using u64 = unsigned long long;

__device__ __forceinline__ u64 fma2(u64 a, u64 b, u64 c) {
    u64 d;
    asm("fma.rn.f32x2 %0, %1, %2, %3;" : "=l"(d) : "l"(a), "l"(b), "l"(c));
    return d;
}
__device__ __forceinline__ u64 add2(u64 a, u64 b) {
    u64 d;
    asm("add.rn.f32x2 %0, %1, %2;" : "=l"(d) : "l"(a), "l"(b));
    return d;
}

template <bool EDGE>
__device__ __forceinline__ u64 ld_row(const char* xb, int p, int w0) {
    if (EDGE) {
        int wg = w0 - HALF_ + p;
        if (wg < 0 || wg >= L_) return 0ull;
    }
    return *reinterpret_cast<const u64*>(xb + (long long)p * (C_ * 4));
}

template <bool EDGE>
__device__ __forceinline__ void conv_body(
    const float* __restrict__ x, const float* __restrict__ w,
    const float* __restrict__ bias, float* __restrict__ out,
    int b, int w0, int cb)
{
    // Base pointer at (b, w0 - HALF, cb). Row stride = 2048 B.
    const char* xb = reinterpret_cast<const char*>(x)
                   + ((long long)((long long)b * L_ + w0 - HALF_) * C_ + cb) * 4ll;

    // Prime the x ring: rows 0..XW_-1  (MLP = 18 at launch).
    u64 xv[XW_];
#pragma unroll
    for (int p = 0; p < XW_; p++)
        xv[p] = ld_row<EDGE>(xb, p, w0);

    u64 acc[T_];
#pragma unroll
    for (int t = 0; t < T_; t++) acc[t] = 0ull;

    // Weight double buffer (per-thread channel pair, L1-resident).
    u64 wcur = *reinterpret_cast<const u64*>(w + cb);

#pragma unroll
    for (int k = 0; k < K_; k++) {
        u64 wnext = 0ull;
        if (k + 1 < K_)
            wnext = *reinterpret_cast<const u64*>(w + (k + 1) * C_ + cb);

#pragma unroll
        for (int t = 0; t < T_; t++)
            acc[t] = fma2(xv[(k + t) % XW_], wcur, acc[t]);

        // Prefetch row k+XW_ into the slot freed by this iteration's t=0 read.
        if (k + XW_ < NP_)
            xv[(k + XW_) % XW_] = ld_row<EDGE>(xb, k + XW_, w0);

        wcur = wnext;
    }

    u64 bv = *reinterpret_cast<const u64*>(bias + cb);
    char* ob = reinterpret_cast<char*>(out)
             + ((long long)((long long)b * L_ + w0) * C_ + cb) * 4ll;
#pragma unroll
    for (int t = 0; t < T_; t++) {
        u64 r = add2(acc[t], bv);
        *reinterpret_cast<u64*>(ob + (long long)t * (C_ * 4)) = r;
    }
}

__global__ __launch_bounds__(256, 3)
void depthconv1d_kernel(const float* __restrict__ x,
                        const float* __restrict__ w,
                        const float* __restrict__ bias,
                        float* __restrict__ out)
{
    int cb   = threadIdx.x * 2;        // channel pair base (0..510)
    int tile = blockIdx.x;             // L tile index
    int b    = blockIdx.y;             // batch
    int w0   = tile * T_;

    if (tile == 0 || tile == (L_ / T_ - 1))
        conv_body<true>(x, w, bias, out, b, w0, cb);
    else
        conv_body<false>(x, w, bias, out, b, w0, cb);
}

extern "C" void kernel_launch(void* const* d_in, const int* in_sizes, int n_in,
                              void* d_out, int out_size)
{
    const float* x    = (const float*)d_in[0];  // [8, 16384, 512]
    const float* ker  = (const float*)d_in[1];  // [31, 512, 1]
    const float* bias = (const float*)d_in[2];  // [512]
    float* out = (float*)d_out;                 // [8, 16384, 512]

    dim3 grid(L_ / T_, B_);   // (1024, 8)
    dim3 block(256);          // 2 channels per thread -> 512 channels
    depthconv1d_kernel<<<grid, block>>>(x, ker, bias, out);
}

// round 4
// speedup vs baseline: 1.1040x; 1.1040x over previous
#include <cuda_runtime.h>
#include <cstdint>

// depthconv1d: B=8, L=16384, C=512, K=31, SAME padding, fp32 NWC.
// out[b,w,c] = sum_k x[b, w+k-15, c] * ker[k*C + c] + bias[c]
//
// R4: cp.async bulk-stage x tile + weights into SMEM (deep MLP, coalesced),
// then k-outer compute with register x-ring sourced from SMEM (29cyc LDS
// latency trivially hidden -> fixes R3's load serialization; no resident
// weights -> fixes R1's register ceiling).
// Block = 128 channels x 32 w, 128 threads. SMEM 47.6KB -> 4 CTAs/SM.

#define B_ 8
#define L_ 16384
#define C_ 512
#define K_ 31
#define HALF_ 15
#define T_ 16        // outputs per thread
#define WB_ 32       // w positions per block
#define CB_ 128      // channels per block
#define NR_ (WB_ + K_ - 1)   // 62 input rows staged
#define XW_ 18       // register x-ring slots
#define NP_ (T_ + K_ - 1)    // 46 rows read per thread

using u64 = unsigned long long;

__device__ __forceinline__ u64 fma2(u64 a, u64 b, u64 c) {
    u64 d;
    asm("fma.rn.f32x2 %0, %1, %2, %3;" : "=l"(d) : "l"(a), "l"(b), "l"(c));
    return d;
}
__device__ __forceinline__ u64 add2(u64 a, u64 b) {
    u64 d;
    asm("add.rn.f32x2 %0, %1, %2;" : "=l"(d) : "l"(a), "l"(b));
    return d;
}
__device__ __forceinline__ void cp_async16(uint32_t smem_addr, const void* gptr) {
    asm volatile("cp.async.cg.shared.global [%0], [%1], 16;"
                 :: "r"(smem_addr), "l"(gptr) : "memory");
}
__device__ __forceinline__ void cp_async_wait_all() {
    asm volatile("cp.async.commit_group;\n\tcp.async.wait_group 0;" ::: "memory");
}

__global__ __launch_bounds__(128, 4)
void depthconv1d_kernel(const float* __restrict__ x,
                        const float* __restrict__ w,
                        const float* __restrict__ bias,
                        float* __restrict__ out)
{
    __shared__ char xs[NR_ * CB_ * 4];      // 62 rows x 512B = 31744B
    __shared__ char ws[K_ * CB_ * 4];       // 31 rows x 512B = 15872B

    const int tid = threadIdx.x;
    const int w0  = blockIdx.x * WB_;       // block's first output w
    const int cb0 = blockIdx.y * CB_;       // block's channel base
    const int b   = blockIdx.z;

    // ---- Stage x tile: rows [w0-15, w0+46] x 512B, 16B chunks ----
    // 32 threads per row (32 x 16B = 512B); 4 rows per iteration.
    {
        const int lane  = tid & 31;         // 16B chunk within row
        const int rbase = tid >> 5;         // row offset 0..3
        const char* gx = reinterpret_cast<const char*>(x)
                       + ((long long)((long long)b * L_) * C_ + cb0) * 4ll;
        uint32_t s0 = (uint32_t)__cvta_generic_to_shared(xs) + lane * 16;
#pragma unroll
        for (int i = 0; i < 16; i++) {
            int r = i * 4 + rbase;
            if (r < NR_) {
                int wg = w0 - HALF_ + r;
                uint32_t sa = s0 + r * (CB_ * 4);
                if ((unsigned)wg < (unsigned)L_) {
                    cp_async16(sa, gx + (long long)wg * (C_ * 4) + lane * 16);
                } else {
                    *reinterpret_cast<uint4*>(xs + r * (CB_ * 4) + lane * 16)
                        = make_uint4(0u, 0u, 0u, 0u);
                }
            }
        }
    }

    // ---- Stage weights: w[k*C + cb0 .. cb0+127] -> ws[k*512B] ----
    {
        // 992 chunks of 16B; 128 threads -> 8 iterations (last partial).
        const char* gw = reinterpret_cast<const char*>(w) + cb0 * 4;
        uint32_t sw = (uint32_t)__cvta_generic_to_shared(ws);
#pragma unroll
        for (int j = 0; j < 8; j++) {
            int chunk = j * 128 + tid;
            if (chunk < (K_ * CB_ * 4) / 16) {
                int o  = chunk * 16;
                int k  = o / (CB_ * 4);
                int of = o % (CB_ * 4);
                cp_async16(sw + o, gw + (long long)k * (C_ * 4) + of);
            }
        }
    }

    cp_async_wait_all();
    __syncthreads();

    // ---- Compute: thread = channel pair x 16 outputs, k-outer, x-ring ----
    const int pair = tid & 63;              // f32x2 lane: channels cb0+2*pair
    const int grp  = tid >> 6;              // w-subgroup 0..1
    const char* xsp = xs + grp * T_ * (CB_ * 4) + pair * 8;
    const char* wsp = ws + pair * 8;

    u64 xv[XW_];
#pragma unroll
    for (int p = 0; p < XW_; p++)
        xv[p] = *reinterpret_cast<const u64*>(xsp + p * (CB_ * 4));

    u64 acc[T_];
#pragma unroll
    for (int t = 0; t < T_; t++) acc[t] = 0ull;

    u64 wcur = *reinterpret_cast<const u64*>(wsp);
#pragma unroll
    for (int k = 0; k < K_; k++) {
        u64 wnext = 0ull;
        if (k + 1 < K_)
            wnext = *reinterpret_cast<const u64*>(wsp + (k + 1) * (CB_ * 4));
#pragma unroll
        for (int t = 0; t < T_; t++)
            acc[t] = fma2(xv[(k + t) % XW_], wcur, acc[t]);
        if (k + XW_ < NP_)
            xv[(k + XW_) % XW_] =
                *reinterpret_cast<const u64*>(xsp + (k + XW_) * (CB_ * 4));
        wcur = wnext;
    }

    u64 bv = *reinterpret_cast<const u64*>(bias + cb0 + pair * 2);
    char* ob = reinterpret_cast<char*>(out)
             + ((long long)((long long)b * L_ + w0 + grp * T_) * C_ + cb0 + pair * 2) * 4ll;
#pragma unroll
    for (int t = 0; t < T_; t++) {
        u64 r = add2(acc[t], bv);
        *reinterpret_cast<u64*>(ob + (long long)t * (C_ * 4)) = r;
    }
}

extern "C" void kernel_launch(void* const* d_in, const int* in_sizes, int n_in,
                              void* d_out, int out_size)
{
    const float* x    = (const float*)d_in[0];  // [8, 16384, 512]
    const float* ker  = (const float*)d_in[1];  // [31, 512, 1]
    const float* bias = (const float*)d_in[2];  // [512]
    float* out = (float*)d_out;                 // [8, 16384, 512]

    dim3 grid(L_ / WB_, C_ / CB_, B_);   // (512, 4, 8) = 16384 blocks
    dim3 block(128);
    depthconv1d_kernel<<<grid, block>>>(x, ker, bias, out);
}